// round 4
// baseline (speedup 1.0000x reference)
#include <cuda_runtime.h>
#include <math.h>

#define NS     64
#define HID    20
#define HDIM   1280
#define BATCH  16384
#define MROWS  8
#define T      512
#define PSTR   1284
#define P6STR  68
#define LVL    806400          // 2016*400 floats per level

// fc2..fc5 scatter weights, target-pair/ci-pair packed:
//   slab si (npairs=(63-si)*10): float4 at [kk*npairs + jp] =
//   (W[j0][ci0], W[j1][ci0], W[j0][ci1], W[j1][ci1]), j0=2jp, j1=2jp+1, ci0=2kk, ci1=2kk+1
__device__ float g_Ws4[4 * LVL];
__device__ float g_W1s[2016 * 20];      // fc1 scalar, j-major
__device__ float g_W6s[2016 * 20];      // fc6 chunk-major (k, t) float4
__device__ float g_Wd [64 * 2020];      // per-si diag: fc2-5 transposed [lv][ci][c], fc6 at 2000

__device__ __forceinline__ int slab_off1(int si) { return 63 * si - (si * (si - 1)) / 2; }

__global__ void prep_scatter(const float* __restrict__ W1, const float* __restrict__ W2,
                             const float* __restrict__ W3, const float* __restrict__ W4,
                             const float* __restrict__ W5, const float* __restrict__ W6)
{
    const int si = blockIdx.x, what = blockIdx.y;
    const int nso1 = 63 - si;
    if (what < 4) {
        const float* W = (what == 0) ? W2 : (what == 1) ? W3 : (what == 2) ? W4 : W5;
        float* dst = g_Ws4 + (size_t)what * LVL + (size_t)slab_off1(si) * 400;
        const int npairs = nso1 * 10;
        const int cnt = nso1 * 400;
        for (int t = threadIdx.x; t < cnt; t += blockDim.x) {
            int m = t & 3, f = t >> 2;
            int jp = f % npairs, kk = f / npairs;
            int j = 2 * jp + (m & 1);
            int so = si + 1 + j / 20, c = j % 20, ci = 2 * kk + (m >> 1);
            dst[t] = W[(size_t)(c * NS + so) * HDIM + ci * NS + si];
        }
    } else if (what == 4) {
        const int nt = nso1 * 20;
        float* d1 = g_W1s + (size_t)slab_off1(si) * 20;
        for (int t = threadIdx.x; t < nt; t += blockDim.x) {
            int so = si + 1 + t / 20, c = t % 20;
            d1[t] = W1[(size_t)(c * NS + so) * NS + si];
        }
        float* dd = g_Wd + (size_t)si * 2020;
        for (int t = threadIdx.x; t < 2020; t += blockDim.x) {
            if (t < 1600) {
                int lv = t / 400, rem = t - lv * 400;
                int ci = rem / 20, c = rem - ci * 20;     // transposed: [ci][c]
                const float* W = (lv == 0) ? W2 : (lv == 1) ? W3 : (lv == 2) ? W4 : W5;
                dd[t] = W[(size_t)(c * NS + si) * HDIM + ci * NS + si];
            } else if (t < 2000) {
                dd[t] = 0.0f;
            } else {
                dd[t] = W6[(size_t)si * HDIM + (t - 2000) * NS + si];
            }
        }
    } else {
        float* d6 = g_W6s + (size_t)slab_off1(si) * 20;
        const int cnt = nso1 * 20;
        for (int t = threadIdx.x; t < cnt; t += blockDim.x) {
            int m = t & 3, q = t >> 2;
            int tt = q % nso1, k = q / nso1;
            int so = si + 1 + tt, ci = 4 * k + m;
            d6[t] = W6[(size_t)so * HDIM + ci * NS + si];
        }
    }
}

// ---- packed f32x2 helpers ----
__device__ __forceinline__ unsigned long long ffma2(unsigned long long a, unsigned long long b,
                                                    unsigned long long c)
{
    unsigned long long d;
    asm("fma.rn.f32x2 %0, %1, %2, %3;" : "=l"(d) : "l"(a), "l"(b), "l"(c));
    return d;
}
__device__ __forceinline__ unsigned long long pack2(float lo, float hi)
{
    unsigned long long v;
    asm("mov.b64 %0, {%1, %2};" : "=l"(v) : "f"(lo), "f"(hi));
    return v;
}
__device__ __forceinline__ float hsum2(unsigned long long v)
{
    float lo, hi;
    asm("mov.b64 {%0, %1}, %2;" : "=f"(lo), "=f"(hi) : "l"(v));
    return lo + hi;
}
__device__ __forceinline__ float sigmoidf(float x) { return 1.0f / (1.0f + expf(-x)); }

#define BAR_SYNC(id)   asm volatile("bar.sync %0, 512;"   :: "r"(id) : "memory")
#define BAR_ARRIVE(id) asm volatile("bar.arrive %0, 512;" :: "r"(id) : "memory")
#define BAR_DIAG()     asm volatile("bar.sync 7, 160;"    ::: "memory")

// fc2..fc5 scatter: thread handles target-pair jp (stride 128) for 2 rows.
__device__ __forceinline__ void scatter_fc25(float* __restrict__ pre,
                                             const unsigned long long* __restrict__ hdu,
                                             int i, int jl, int r0, int r1, bool gated)
{
    const int npairs = (63 - i) * 10;
    const int tbase = (i + 1) * HID;
    const size_t soff = (size_t)slab_off1(i) * 400;
    #pragma unroll 1
    for (int l = 0; l < 4; ++l) {
        if (gated) { int b = l + 1; BAR_SYNC(b); }
        if (jl < npairs) {
            const ulonglong2* wb = (const ulonglong2*)(g_Ws4 + (size_t)l * LVL + soff);
            float* prl = pre + (size_t)(l + 1) * MROWS * PSTR + tbase;
            unsigned long long h0[20], h1[20];
            {
                const ulonglong2* p0 = (const ulonglong2*)(hdu + (l * MROWS + r0) * HID);
                const ulonglong2* p1 = (const ulonglong2*)(hdu + (l * MROWS + r1) * HID);
                #pragma unroll
                for (int q = 0; q < 10; ++q) {
                    ulonglong2 a = p0[q]; h0[2*q] = a.x; h0[2*q+1] = a.y;
                    ulonglong2 b = p1[q]; h1[2*q] = b.x; h1[2*q+1] = b.y;
                }
            }
            for (int jp = jl; jp < npairs; jp += 128) {
                unsigned long long* d0 = (unsigned long long*)(prl + r0 * PSTR + 2 * jp);
                unsigned long long* d1 = (unsigned long long*)(prl + r1 * PSTR + 2 * jp);
                unsigned long long a0 = *d0, a1 = *d1;
                const ulonglong2* wp = wb + jp;
                #pragma unroll
                for (int kk = 0; kk < 10; ++kk) {
                    ulonglong2 wv = *wp; wp += npairs;
                    a0 = ffma2(wv.x, h0[2*kk],   a0);
                    a0 = ffma2(wv.y, h0[2*kk+1], a0);
                    a1 = ffma2(wv.x, h1[2*kk],   a1);
                    a1 = ffma2(wv.y, h1[2*kk+1], a1);
                }
                *d0 = a0; *d1 = a1;
            }
        }
    }
}

__global__ void __launch_bounds__(T, 1)
net_kernel(const float* __restrict__ u, float* __restrict__ out)
{
    extern __shared__ float sm[];
    unsigned long long* hdu = (unsigned long long*)sm;            // [5][8][20] dup-packed
    unsigned long long* sd  = (unsigned long long*)(sm + 1600);   // [8] dup sample
    float* h5b  = sm + 1616;                                      // [160] h5 scalar
    float* pre  = sm + 1776;                                      // [5][8][PSTR]
    float* pre6 = sm + 53136;                                     // [8][P6STR]
    float* usm  = sm + 53680;                                     // [8][64]
    float* wd   = sm + 54192;                                     // [2020]

    const int tid = threadIdx.x;
    const int pair = tid & 3, jl = tid >> 2;
    const int r0 = 2 * pair, r1 = r0 + 1;

    for (int k = tid; k < 5 * MROWS * PSTR; k += T) pre[k] = 0.0f;
    for (int k = tid; k < MROWS * P6STR; k += T) pre6[k] = 0.0f;
    { int ii = tid >> 3, rr = tid & 7;
      usm[rr * NS + ii] = u[(size_t)ii * BATCH + (size_t)blockIdx.x * MROWS + rr]; }
    for (int k = tid; k < 2020; k += T) wd[k] = g_Wd[k];
    __syncthreads();

    const bool is_diag = (tid < 160);

    for (int i = 0; i < NS; ++i) {
        if (is_diag) {
            // ===== diagonal chain (producer) =====
            const int r = tid / 20, c = tid - (tid / 20) * 20;
            float v = sigmoidf(pre[r * PSTR + i * HID + c]);          // h1
            hdu[r * HID + c] = pack2(v, v);
            BAR_ARRIVE(1); BAR_DIAG();
            #pragma unroll 1
            for (int lv = 0; lv < 4; ++lv) {
                float acc = pre[((lv + 1) * MROWS + r) * PSTR + i * HID + c];
                const float* w  = wd + lv * 400 + c;                  // [ci*20 + c]
                const float* hh = (const float*)(hdu + (lv * MROWS + r) * HID);
                #pragma unroll
                for (int ci = 0; ci < 20; ++ci) acc = fmaf(w[ci * 20], hh[2 * ci], acc);
                v = sigmoidf(acc);
                hdu[((lv + 1) * MROWS + r) * HID + c] = pack2(v, v);
                if (lv == 3) h5b[r * HID + c] = v;
                { int b = lv + 2; BAR_ARRIVE(b); }
                BAR_DIAG();
            }
            if (tid < MROWS) {                                        // fc6 diag + sample
                const int rr = tid;
                float acc = pre6[rr * P6STR + i];
                #pragma unroll
                for (int ci = 0; ci < 20; ++ci) acc = fmaf(wd[2000 + ci], h5b[rr * HID + ci], acc);
                float x = sigmoidf(acc);
                out[((size_t)blockIdx.x * MROWS + rr) * NS + i] = x;
                float s = (x >= usm[rr * NS + i]) ? 1.0f : -1.0f;
                sd[rr] = pack2(s, s);
            }
            BAR_DIAG();
            BAR_ARRIVE(6);
            // join scatter (own jp share), then prefetch next diag weights
            scatter_fc25(pre, hdu, i, jl, r0, r1, false);
            if (i < 63) {
                const float* src = g_Wd + (size_t)(i + 1) * 2020;
                for (int k = tid; k < 2020; k += 160) wd[k] = src[k];
            }
        } else {
            // ===== consumer warps: gated scatter, then fc6 + fc1 =====
            scatter_fc25(pre, hdu, i, jl, r0, r1, true);
            BAR_SYNC(5);
            const int idx = tid - 160;
            const int nso1 = 63 - i;
            {
                const int jj = idx >> 2;
                if (jj < nso1) {
                    const float* wb6 = g_W6s + (size_t)slab_off1(i) * 20;
                    const ulonglong2* hp0 = (const ulonglong2*)(h5b + r0 * HID);
                    const ulonglong2* hp1 = (const ulonglong2*)(h5b + r1 * HID);
                    float* d0p = pre6 + r0 * P6STR + (i + 1 + jj);
                    float* d1p = pre6 + r1 * P6STR + (i + 1 + jj);
                    unsigned long long a0 = pack2(*d0p, 0.0f);
                    unsigned long long a1 = pack2(*d1p, 0.0f);
                    #pragma unroll
                    for (int k = 0; k < 5; ++k) {
                        ulonglong2 wv = *(const ulonglong2*)(wb6 + ((size_t)k * nso1 + jj) * 4);
                        ulonglong2 h0v = hp0[k], h1v = hp1[k];
                        a0 = ffma2(wv.x, h0v.x, a0); a0 = ffma2(wv.y, h0v.y, a0);
                        a1 = ffma2(wv.x, h1v.x, a1); a1 = ffma2(wv.y, h1v.y, a1);
                    }
                    *d0p = hsum2(a0);
                    *d1p = hsum2(a1);
                }
            }
            BAR_SYNC(6);
            {
                const int npairs = nso1 * 10;
                const int jpl = idx >> 2;                 // 0..87
                const float* wb1 = g_W1s + (size_t)slab_off1(i) * 20;
                float* p0 = pre + r0 * PSTR + (i + 1) * HID;
                float* p1 = pre + r1 * PSTR + (i + 1) * HID;
                unsigned long long s0 = sd[r0], s1 = sd[r1];
                for (int jp = jpl; jp < npairs; jp += 88) {
                    unsigned long long w2 = *(const unsigned long long*)(wb1 + 2 * jp);
                    unsigned long long* a0p = (unsigned long long*)(p0 + 2 * jp);
                    unsigned long long* a1p = (unsigned long long*)(p1 + 2 * jp);
                    *a0p = ffma2(w2, s0, *a0p);
                    *a1p = ffma2(w2, s1, *a1p);
                }
            }
        }
        __syncthreads();
    }
}

extern "C" void kernel_launch(void* const* d_in, const int* in_sizes, int n_in,
                              void* d_out, int out_size)
{
    (void)in_sizes; (void)n_in; (void)out_size;
    const float* u  = (const float*)d_in[1];
    const float* W1 = (const float*)d_in[2];
    const float* W2 = (const float*)d_in[3];
    const float* W3 = (const float*)d_in[4];
    const float* W4 = (const float*)d_in[5];
    const float* W5 = (const float*)d_in[6];
    const float* W6 = (const float*)d_in[7];
    float* out = (float*)d_out;

    dim3 pg(64, 6);
    prep_scatter<<<pg, 256>>>(W1, W2, W3, W4, W5, W6);

    const int smem_bytes = 56212 * (int)sizeof(float);   // 224,848 B
    cudaFuncSetAttribute(net_kernel, cudaFuncAttributeMaxDynamicSharedMemorySize, smem_bytes);
    net_kernel<<<BATCH / MROWS, T, smem_bytes>>>(u, out);
}

// round 5
// speedup vs baseline: 1.3006x; 1.3006x over previous
#include <cuda_runtime.h>
#include <math.h>

#define NS     64
#define HID    20
#define HDIM   1280
#define BATCH  16384
#define MROWS  8
#define T      1024
#define PSTR   1284
#define P6STR  68
#define LVL    806400          // 2016*400 floats per level (no diag)

typedef unsigned long long ull;

// Scatter weights target-major: slab si has nt=(63-si)*20 targets, 20 floats each:
//   g_Ws[l][slab + j*20 + ci] = W_{l+1}[(c*64+so)*1280 + ci*64 + si], j=(so-si-1)*20+c
__device__ float g_Ws[4 * LVL];
__device__ float g_W1s[2016 * 20];      // fc1: [slab + j]
__device__ float g_W6s[2016 * 20];      // fc6: [slab + t*20 + ci]
__device__ float g_Wd [64 * 2020];      // diag per si: [lv*400 + ci*20 + c], fc6 at 2000

__device__ __forceinline__ int slab_off1(int si) { return 63 * si - (si * (si - 1)) / 2; }

__global__ void prep_scatter(const float* __restrict__ W1, const float* __restrict__ W2,
                             const float* __restrict__ W3, const float* __restrict__ W4,
                             const float* __restrict__ W5, const float* __restrict__ W6)
{
    const int si = blockIdx.x, what = blockIdx.y;
    const int nso1 = 63 - si;
    const int nt = nso1 * 20;
    if (what < 4) {
        const float* W = (what == 0) ? W2 : (what == 1) ? W3 : (what == 2) ? W4 : W5;
        float* dst = g_Ws + (size_t)what * LVL + (size_t)slab_off1(si) * 400;
        const int cnt = nso1 * 400;
        for (int t = threadIdx.x; t < cnt; t += blockDim.x) {
            int j = t / 20, ci = t - j * 20;
            int so = si + 1 + j / 20, c = j % 20;
            dst[t] = W[(size_t)(c * NS + so) * HDIM + ci * NS + si];
        }
    } else if (what == 4) {
        float* d1 = g_W1s + (size_t)slab_off1(si) * 20;
        for (int t = threadIdx.x; t < nt; t += blockDim.x) {
            int so = si + 1 + t / 20, c = t % 20;
            d1[t] = W1[(size_t)(c * NS + so) * NS + si];
        }
        float* dd = g_Wd + (size_t)si * 2020;
        for (int t = threadIdx.x; t < 2020; t += blockDim.x) {
            if (t < 1600) {
                int lv = t / 400, rem = t - lv * 400;
                int ci = rem / 20, c = rem - ci * 20;
                const float* W = (lv == 0) ? W2 : (lv == 1) ? W3 : (lv == 2) ? W4 : W5;
                dd[t] = W[(size_t)(c * NS + si) * HDIM + ci * NS + si];
            } else if (t < 2000) {
                dd[t] = 0.0f;
            } else {
                dd[t] = W6[(size_t)si * HDIM + (t - 2000) * NS + si];
            }
        }
    } else {
        float* d6 = g_W6s + (size_t)slab_off1(si) * 20;
        for (int t = threadIdx.x; t < nt; t += blockDim.x) {
            int tt = t / 20, ci = t - tt * 20;
            int so = si + 1 + tt;
            d6[t] = W6[(size_t)so * HDIM + ci * NS + si];
        }
    }
}

__device__ __forceinline__ ull ffma2(ull a, ull b, ull c)
{
    ull d;
    asm("fma.rn.f32x2 %0, %1, %2, %3;" : "=l"(d) : "l"(a), "l"(b), "l"(c));
    return d;
}
__device__ __forceinline__ ull pack2(float lo, float hi)
{
    ull v;
    asm("mov.b64 %0, {%1, %2};" : "=l"(v) : "f"(lo), "f"(hi));
    return v;
}
__device__ __forceinline__ float hsum2(ull v)
{
    float lo, hi;
    asm("mov.b64 {%0, %1}, %2;" : "=f"(lo), "=f"(hi) : "l"(v));
    return lo + hi;
}
__device__ __forceinline__ float sigmoidf(float x) { return 1.0f / (1.0f + expf(-x)); }

#define BAR_DIAG() asm volatile("bar.sync 1, 160;" ::: "memory")

__global__ void __launch_bounds__(T, 1)
net_kernel(const float* __restrict__ u, float* __restrict__ out)
{
    extern __shared__ float sm[];
    float* pre  = sm;                       // [5][8][PSTR]  (level 0 = pre1)
    float* pre6 = pre + 5 * MROWS * PSTR;   // [8][P6STR]
    float* hbt  = pre6 + MROWS * P6STR;     // [5][8][20] scalar h
    float* usm  = hbt + 5 * 160;            // [8][64]
    float* wd   = usm + 512;                // [2020]
    float* sv   = wd + 2020;                // [8] sampled +/-1

    const int tid = threadIdx.x;
    const int r  = tid & 7;
    const int jj = tid >> 3;                // 0..127

    for (int k = tid; k < 5 * MROWS * PSTR; k += T) pre[k] = 0.0f;
    for (int k = tid; k < MROWS * P6STR; k += T) pre6[k] = 0.0f;
    if (tid < 512) {
        int ii = tid >> 3, rr = tid & 7;
        usm[rr * NS + ii] = u[(size_t)ii * BATCH + (size_t)blockIdx.x * MROWS + rr];
    }
    for (int k = tid; k < 2020; k += T) wd[k] = g_Wd[k];
    __syncthreads();

    for (int i = 0; i < NS; ++i) {
        // ===== diagonal chain: 160 threads, named barriers; others wait below =====
        if (tid < 160) {
            const int dr = tid / 20, dc = tid - (tid / 20) * 20;
            hbt[dr * 20 + dc] = sigmoidf(pre[dr * PSTR + i * HID + dc]);
            BAR_DIAG();
            #pragma unroll 1
            for (int lv = 0; lv < 4; ++lv) {
                float acc = pre[((lv + 1) * MROWS + dr) * PSTR + i * HID + dc];
                const float* w  = wd + lv * 400 + dc;          // [ci*20 + c]
                const float* hh = hbt + lv * 160 + dr * 20;
                #pragma unroll
                for (int ci = 0; ci < 20; ++ci) acc = fmaf(w[ci * 20], hh[ci], acc);
                hbt[(lv + 1) * 160 + dr * 20 + dc] = sigmoidf(acc);
                BAR_DIAG();
            }
            if (tid < MROWS) {                                 // fc6 diag + sample
                float acc = pre6[tid * P6STR + i];
                const float* hh = hbt + 4 * 160 + tid * 20;
                #pragma unroll
                for (int ci = 0; ci < 20; ++ci) acc = fmaf(wd[2000 + ci], hh[ci], acc);
                float x = sigmoidf(acc);
                out[((size_t)blockIdx.x * MROWS + tid) * NS + i] = x;
                sv[tid] = (x >= usm[tid * NS + i]) ? 1.0f : -1.0f;
            }
        }
        __syncthreads();

        // ===== scatter phase =====
        if (i < 63) {
            const int nso1 = 63 - i;
            const int nt = nso1 * HID;
            const int tbase = (i + 1) * HID;
            const size_t soff = (size_t)slab_off1(i);

            // fc2..fc5: thread (r, jj) accumulates pre[l+1][r][tbase+j]
            #pragma unroll 1
            for (int l = 0; l < 4; ++l) {
                const float* wb = g_Ws + (size_t)l * LVL + soff * 400;
                float* prl = pre + (size_t)(l + 1) * MROWS * PSTR + r * PSTR + tbase;
                const ull* hp = (const ull*)(hbt + l * 160 + r * 20);
                ull h0 = hp[0], h1 = hp[1], h2 = hp[2], h3 = hp[3], h4 = hp[4];
                ull h5 = hp[5], h6 = hp[6], h7 = hp[7], h8 = hp[8], h9 = hp[9];
                #pragma unroll 1
                for (int j = jj; j < nt; j += 128) {
                    const ulonglong2* wp = (const ulonglong2*)(wb + (size_t)j * 20);
                    ulonglong2 wa = wp[0], wbv = wp[1], wc = wp[2], wdv = wp[3], we = wp[4];
                    float* dp = prl + j;
                    ull a0 = pack2(*dp, 0.0f);
                    ull a1 = pack2(0.0f, 0.0f);
                    a0 = ffma2(wa.x,  h0, a0); a1 = ffma2(wa.y,  h1, a1);
                    a0 = ffma2(wbv.x, h2, a0); a1 = ffma2(wbv.y, h3, a1);
                    a0 = ffma2(wc.x,  h4, a0); a1 = ffma2(wc.y,  h5, a1);
                    a0 = ffma2(wdv.x, h6, a0); a1 = ffma2(wdv.y, h7, a1);
                    a0 = ffma2(we.x,  h8, a0); a1 = ffma2(we.y,  h9, a1);
                    *dp = hsum2(a0) + hsum2(a1);
                }
            }
            // fc6: thread (r, jj<nso1) accumulates pre6[r][i+1+jj]
            if (jj < nso1) {
                const float* wb6 = g_W6s + soff * 20;
                const ull* hp = (const ull*)(hbt + 4 * 160 + r * 20);
                const ulonglong2* wp = (const ulonglong2*)(wb6 + (size_t)jj * 20);
                ulonglong2 wa = wp[0], wbv = wp[1], wc = wp[2], wdv = wp[3], we = wp[4];
                float* dp = pre6 + r * P6STR + (i + 1 + jj);
                ull a0 = pack2(*dp, 0.0f);
                ull a1 = pack2(0.0f, 0.0f);
                a0 = ffma2(wa.x,  hp[0], a0); a1 = ffma2(wa.y,  hp[1], a1);
                a0 = ffma2(wbv.x, hp[2], a0); a1 = ffma2(wbv.y, hp[3], a1);
                a0 = ffma2(wc.x,  hp[4], a0); a1 = ffma2(wc.y,  hp[5], a1);
                a0 = ffma2(wdv.x, hp[6], a0); a1 = ffma2(wdv.y, hp[7], a1);
                a0 = ffma2(we.x,  hp[8], a0); a1 = ffma2(we.y,  hp[9], a1);
                *dp = hsum2(a0) + hsum2(a1);
            }
            // fc1 rank-1: thread (r, jj) strides targets
            {
                const float* wb1 = g_W1s + soff * 20;
                float* p1 = pre + r * PSTR + tbase;
                const float s = sv[r];
                for (int j = jj; j < nt; j += 128)
                    p1[j] = fmaf(wb1[j], s, p1[j]);
            }
            // prefetch next step's diag weights (wd reads all done pre-sync)
            {
                const float* src = g_Wd + (size_t)(i + 1) * 2020;
                for (int k = tid; k < 2020; k += T) wd[k] = src[k];
            }
        }
        __syncthreads();
    }
}

extern "C" void kernel_launch(void* const* d_in, const int* in_sizes, int n_in,
                              void* d_out, int out_size)
{
    (void)in_sizes; (void)n_in; (void)out_size;
    const float* u  = (const float*)d_in[1];
    const float* W1 = (const float*)d_in[2];
    const float* W2 = (const float*)d_in[3];
    const float* W3 = (const float*)d_in[4];
    const float* W4 = (const float*)d_in[5];
    const float* W5 = (const float*)d_in[6];
    const float* W6 = (const float*)d_in[7];
    float* out = (float*)d_out;

    dim3 pg(64, 6);
    prep_scatter<<<pg, 256>>>(W1, W2, W3, W4, W5, W6);

    const int smem_bytes = (5 * MROWS * PSTR + MROWS * P6STR + 5 * 160
                            + 512 + 2020 + 8) * (int)sizeof(float);   // ~221 KB
    cudaFuncSetAttribute(net_kernel, cudaFuncAttributeMaxDynamicSharedMemorySize, smem_bytes);
    net_kernel<<<BATCH / MROWS, T, smem_bytes>>>(u, out);
}